// round 8
// baseline (speedup 1.0000x reference)
#include <cuda_runtime.h>

// Problem constants
#define Bn   32
#define Cn   128
#define Tn   8192
#define Kn   5
#define MCn  256          // M*C
#define PADn 2

// conv tiling
#define OT   64           // output-channel tile
#define TT   128          // time tile
#define ICC  16           // input-channel chunk

// Scratch (no cudaMalloc allowed)
__device__ float g_gap[Bn * Cn];
__device__ float g_h[Bn * MCn];

// ---------------------------------------------------------------------------
// Stage 1: masked global average pool.  gap[b,c] = sum_t x[b,c,t] / len[b]
// One block per (b,c) row; float4 strided reads; memory-bound.
// ---------------------------------------------------------------------------
__global__ void gap_kernel(const float* __restrict__ x, const int* __restrict__ lens) {
    int bc = blockIdx.x;  // b*Cn + c
    const float4* row = reinterpret_cast<const float4*>(x + (size_t)bc * Tn);
    float s = 0.f;
    for (int i = threadIdx.x; i < Tn / 4; i += blockDim.x) {
        float4 v = row[i];
        s += (v.x + v.y) + (v.z + v.w);
    }
    for (int o = 16; o; o >>= 1) s += __shfl_down_sync(0xffffffffu, s, o);
    __shared__ float sm[8];
    int w = threadIdx.x >> 5, l = threadIdx.x & 31;
    if (l == 0) sm[w] = s;
    __syncthreads();
    if (threadIdx.x == 0) {
        float tot = 0.f;
        #pragma unroll
        for (int i = 0; i < 8; i++) tot += sm[i];
        g_gap[bc] = tot / (float)lens[bc / Cn];
    }
}

// ---------------------------------------------------------------------------
// Stage 2: h[b,j] = sigmoid(gap[b,:] . w1[j,:] + b1[j]).  32 blocks x 256 thr.
// ---------------------------------------------------------------------------
__global__ void fc1_kernel(const float* __restrict__ w1, const float* __restrict__ b1) {
    int b = blockIdx.x;
    __shared__ float sg[Cn];
    if (threadIdx.x < Cn) sg[threadIdx.x] = g_gap[b * Cn + threadIdx.x];
    __syncthreads();
    int j = threadIdx.x;  // 256 threads == MCn
    const float* wr = w1 + (size_t)j * Cn;
    float z = b1[j];
    #pragma unroll 8
    for (int c = 0; c < Cn; c++) z += sg[c] * wr[c];
    g_h[b * MCn + j] = 1.f / (1.f + expf(-z));
}

// ---------------------------------------------------------------------------
// Stage 3: dynamic per-sample conv.
// out[b,o,t] = sum_{i,k} (w2[o*640+i*5+k] * h[b, 2o + (i>=64)]) * x[b,i,t+k-2]
// Block tile: 64 o x 128 t, one b. Thread tile: 4 o x 8 t, packed as f32x2
// pairs (4 accum pairs per o). Weights premultiplied by h and stored as
// duplicated float2 in shared -> LDS.64 gives ready-packed operand.
// ---------------------------------------------------------------------------
__global__ __launch_bounds__(256, 2)
void conv_kernel(const float* __restrict__ x, const float* __restrict__ w2,
                 float* __restrict__ out) {
    const int t0 = blockIdx.x * TT;
    const int o0 = blockIdx.y * OT;
    const int b  = blockIdx.z;

    __shared__ float2 sW[OT * ICC * Kn];             // [o][i][k], value duplicated
    __shared__ __align__(16) float sX[ICC][TT + 4];  // halo of K-1 = 4
    __shared__ float sH[2 * OT];

    const int tx = threadIdx.x;   // 16 -> time
    const int ty = threadIdx.y;   // 16 -> out-channel
    const int tid = ty * 16 + tx;

    if (tid < 2 * OT) sH[tid] = g_h[b * MCn + 2 * o0 + tid];

    unsigned long long acc[4][4];
    #pragma unroll
    for (int oo = 0; oo < 4; oo++)
        #pragma unroll
        for (int p = 0; p < 4; p++) acc[oo][p] = 0ull;

    for (int ic0 = 0; ic0 < Cn; ic0 += ICC) {
        __syncthreads();  // previous compute done (and sH visible on 1st iter)

        // fill weight tile: e = o*(ICC*Kn) + i*Kn + k  (linear in both read+write)
        for (int e = tid; e < OT * ICC * Kn; e += 256) {
            int o = e / (ICC * Kn);
            int r = e - o * (ICC * Kn);
            int i = r / Kn;
            float wv = w2[(size_t)(o0 + o) * (Cn * Kn) + ic0 * Kn + r];
            float v  = wv * sH[2 * o + ((ic0 + i) >= 64 ? 1 : 0)];
            sW[e] = make_float2(v, v);
        }
        // fill x tile with halo
        for (int e = tid; e < ICC * (TT + 4); e += 256) {
            int i = e / (TT + 4);
            int c = e - i * (TT + 4);
            int t = t0 - PADn + c;
            sX[i][c] = (t >= 0 && t < Tn)
                       ? x[((size_t)(b * Cn + ic0 + i)) * Tn + t] : 0.f;
        }
        __syncthreads();

        const unsigned long long* sWu =
            reinterpret_cast<const unsigned long long*>(sW);

        #pragma unroll 4
        for (int i = 0; i < ICC; i++) {
            const float4* xr = reinterpret_cast<const float4*>(&sX[i][tx * 8]);
            float4 a0 = xr[0], a1 = xr[1], a2 = xr[2];
            float xv[12] = {a0.x, a0.y, a0.z, a0.w,
                            a1.x, a1.y, a1.z, a1.w,
                            a2.x, a2.y, a2.z, a2.w};
            unsigned long long xp[11];
            #pragma unroll
            for (int j = 0; j < 11; j++)
                asm("mov.b64 %0, {%1, %2};" : "=l"(xp[j]) : "f"(xv[j]), "f"(xv[j + 1]));

            #pragma unroll
            for (int oo = 0; oo < 4; oo++) {
                const unsigned long long* wr =
                    sWu + ((size_t)(ty * 4 + oo) * ICC + i) * Kn;
                #pragma unroll
                for (int k = 0; k < Kn; k++) {
                    unsigned long long ww = wr[k];
                    #pragma unroll
                    for (int p = 0; p < 4; p++)
                        asm("fma.rn.f32x2 %0, %1, %2, %0;"
                            : "+l"(acc[oo][p]) : "l"(ww), "l"(xp[2 * p + k]));
                }
            }
        }
    }

    // store 4 o x 8 t per thread as float2
    const int obase = b * Cn + o0 + ty * 4;
    #pragma unroll
    for (int oo = 0; oo < 4; oo++) {
        float* orow = out + (size_t)(obase + oo) * Tn + t0 + tx * 8;
        #pragma unroll
        for (int p = 0; p < 4; p++) {
            float lo, hi;
            asm("mov.b64 {%0, %1}, %2;" : "=f"(lo), "=f"(hi) : "l"(acc[oo][p]));
            reinterpret_cast<float2*>(orow)[p] = make_float2(lo, hi);
        }
    }
}

// ---------------------------------------------------------------------------
extern "C" void kernel_launch(void* const* d_in, const int* in_sizes, int n_in,
                              void* d_out, int out_size) {
    const float* x    = (const float*)d_in[0];
    const int*   lens = (const int*)  d_in[1];
    const float* w1   = (const float*)d_in[2];
    const float* b1   = (const float*)d_in[3];
    const float* w2   = (const float*)d_in[4];
    float* out = (float*)d_out;

    gap_kernel<<<Bn * Cn, 256>>>(x, lens);
    fc1_kernel<<<Bn, 256>>>(w1, b1);
    conv_kernel<<<dim3(Tn / TT, Cn / OT, Bn), dim3(16, 16)>>>(x, w2, out);
}

// round 9
// speedup vs baseline: 1.2935x; 1.2935x over previous
#include <cuda_runtime.h>

// Problem constants
#define Bn   32
#define Cn   128
#define Tn   8192
#define Kn   5
#define MCn  256          // M*C
#define OT   64           // output-channel tile
#define TT   128          // time tile
#define ICC  16           // input-channel chunk
#define NCH  (Cn / ICC)   // 8 chunks
#define XROW 144          // floats per x smem row (TT + 16 halo, 16B-aligned chunks)
#define WTILE (OT * ICC * Kn)            // 5120 float2 per weight tile
#define SMEM_BYTES (2 * WTILE * 8 + 2 * ICC * XROW * 4)   // 81920 + 18432 = 100352

// Scratch (no cudaMalloc allowed)
__device__ float  g_gap[Bn * Cn];
__device__ float  g_h[Bn * MCn];
// Precomputed dynamic weights, duplicated float2, tile-contiguous:
// layout [b][oc(2)][ic(8)][o(64)][i(16)][k(5)]
__device__ float2 g_wd[(size_t)Bn * 2 * NCH * WTILE];

// ---------------------------------------------------------------------------
// Stage 1: masked global average pool.
// ---------------------------------------------------------------------------
__global__ void gap_kernel(const float* __restrict__ x, const int* __restrict__ lens) {
    int bc = blockIdx.x;
    const float4* row = reinterpret_cast<const float4*>(x + (size_t)bc * Tn);
    float s = 0.f;
    for (int i = threadIdx.x; i < Tn / 4; i += blockDim.x) {
        float4 v = row[i];
        s += (v.x + v.y) + (v.z + v.w);
    }
    for (int o = 16; o; o >>= 1) s += __shfl_down_sync(0xffffffffu, s, o);
    __shared__ float sm[8];
    int w = threadIdx.x >> 5, l = threadIdx.x & 31;
    if (l == 0) sm[w] = s;
    __syncthreads();
    if (threadIdx.x == 0) {
        float tot = 0.f;
        #pragma unroll
        for (int i = 0; i < 8; i++) tot += sm[i];
        g_gap[bc] = tot / (float)lens[bc / Cn];
    }
}

// ---------------------------------------------------------------------------
// Stage 2: h = sigmoid(gap @ w1^T + b1)
// ---------------------------------------------------------------------------
__global__ void fc1_kernel(const float* __restrict__ w1, const float* __restrict__ b1) {
    int b = blockIdx.x;
    __shared__ float sg[Cn];
    if (threadIdx.x < Cn) sg[threadIdx.x] = g_gap[b * Cn + threadIdx.x];
    __syncthreads();
    int j = threadIdx.x;
    const float* wr = w1 + (size_t)j * Cn;
    float z = b1[j];
    #pragma unroll 8
    for (int c = 0; c < Cn; c++) z += sg[c] * wr[c];
    g_h[b * MCn + j] = 1.f / (1.f + expf(-z));
}

// ---------------------------------------------------------------------------
// Stage 2.5: materialize dynamic weights wd = w2 * h into tile-contiguous,
// duplicated-float2 layout (so the conv can cp.async it verbatim).
// ---------------------------------------------------------------------------
__global__ void wd_kernel(const float* __restrict__ w2) {
    int idx = blockIdx.x * 256 + threadIdx.x;   // 2,621,440 total, exact grid
    int k = idx % Kn;
    int r = idx / Kn;
    int i = r % ICC; r /= ICC;
    int o = r % OT;  r /= OT;
    int ic = r % NCH; r /= NCH;
    int oc = r % 2;
    int b  = r / 2;
    int O = oc * OT + o;
    int I = ic * ICC + i;
    float v = w2[(size_t)O * (Cn * Kn) + I * Kn + k] *
              g_h[b * MCn + 2 * O + (I >= 64 ? 1 : 0)];
    g_wd[idx] = make_float2(v, v);
}

// ---------------------------------------------------------------------------
// cp.async prefetch of one (weight tile, x tile) pair into buffer `buf`.
// ---------------------------------------------------------------------------
__device__ __forceinline__ void prefetch_tiles(
    const float2* __restrict__ wd_tile, const float* __restrict__ xb,
    int t0, int buf, float2* sW, float* sX, int tid)
{
    // weight tile: contiguous 40960 B -> 2560 x 16B
    const float4* ws = reinterpret_cast<const float4*>(wd_tile);
    float4* wdst = reinterpret_cast<float4*>(sW + buf * WTILE);
    #pragma unroll
    for (int e = 0; e < 10; e++) {
        int idx = e * 256 + tid;
        unsigned du = (unsigned)__cvta_generic_to_shared(wdst + idx);
        asm volatile("cp.async.cg.shared.global [%0], [%1], 16;"
                     :: "r"(du), "l"(ws + idx) : "memory");
    }
    // x tile: ICC rows x 36 16B chunks, gmem base t0-8 (16B aligned)
    #pragma unroll
    for (int e0 = 0; e0 < 3; e0++) {
        int e = e0 * 256 + tid;
        if (e < ICC * 36) {
            int i = e / 36;
            int j = e - i * 36;
            int g = t0 - 8 + 4 * j;
            float* d = sX + (buf * ICC + i) * XROW + 4 * j;
            const float* s = xb + (size_t)i * Tn + g;
            if (g >= 0 && g + 4 <= Tn) {
                unsigned du = (unsigned)__cvta_generic_to_shared(d);
                asm volatile("cp.async.cg.shared.global [%0], [%1], 16;"
                             :: "r"(du), "l"(s) : "memory");
            } else {
                #pragma unroll
                for (int q = 0; q < 4; q++)
                    d[q] = (g + q >= 0 && g + q < Tn) ? s[q] : 0.f;
            }
        }
    }
    asm volatile("cp.async.commit_group;" ::: "memory");
}

// ---------------------------------------------------------------------------
// Stage 3: dynamic conv, double-buffered cp.async pipeline + packed FFMA2.
// ---------------------------------------------------------------------------
__global__ __launch_bounds__(256, 2)
void conv_kernel(const float* __restrict__ x, float* __restrict__ out) {
    extern __shared__ __align__(16) char smem_raw[];
    float2* sW = reinterpret_cast<float2*>(smem_raw);                       // [2][WTILE]
    float*  sX = reinterpret_cast<float*>(smem_raw + 2 * WTILE * sizeof(float2)); // [2][ICC][XROW]

    const int t0 = blockIdx.x * TT;
    const int ob = blockIdx.y;
    const int b  = blockIdx.z;
    const int tid = threadIdx.x;
    const int tx = tid & 15;
    const int ty = tid >> 4;

    const float2* wd_base = g_wd + (size_t)(b * 2 + ob) * (NCH * WTILE);
    const float* xb = x + (size_t)b * Cn * Tn;

    unsigned long long acc[4][4];
    #pragma unroll
    for (int a = 0; a < 4; a++)
        #pragma unroll
        for (int p = 0; p < 4; p++) acc[a][p] = 0ull;

    prefetch_tiles(wd_base, xb, t0, 0, sW, sX, tid);

    for (int ic = 0; ic < NCH; ic++) {
        if (ic + 1 < NCH) {
            prefetch_tiles(wd_base + (size_t)(ic + 1) * WTILE,
                           xb + (size_t)(ic + 1) * ICC * Tn,
                           t0, (ic + 1) & 1, sW, sX, tid);
            asm volatile("cp.async.wait_group 1;" ::: "memory");
        } else {
            asm volatile("cp.async.wait_group 0;" ::: "memory");
        }
        __syncthreads();

        const unsigned long long* wbuf =
            reinterpret_cast<const unsigned long long*>(sW + (ic & 1) * WTILE);
        const float* xbuf = sX + (ic & 1) * ICC * XROW;

        #pragma unroll 4
        for (int i = 0; i < ICC; i++) {
            // need smem window [tx*8+6, tx*8+17]; load aligned f4 at +4..+16
            const float4* xr = reinterpret_cast<const float4*>(xbuf + i * XROW + tx * 8 + 4);
            float4 a0 = xr[0], a1 = xr[1], a2 = xr[2], a3 = xr[3];
            float f[16] = {a0.x, a0.y, a0.z, a0.w, a1.x, a1.y, a1.z, a1.w,
                           a2.x, a2.y, a2.z, a2.w, a3.x, a3.y, a3.z, a3.w};
            unsigned long long xp[11];
            #pragma unroll
            for (int j = 0; j < 11; j++)
                asm("mov.b64 %0, {%1, %2};" : "=l"(xp[j]) : "f"(f[j + 2]), "f"(f[j + 3]));

            #pragma unroll
            for (int oo = 0; oo < 4; oo++) {
                const unsigned long long* wr = wbuf + ((ty * 4 + oo) * ICC + i) * Kn;
                #pragma unroll
                for (int k = 0; k < Kn; k++) {
                    unsigned long long ww = wr[k];
                    #pragma unroll
                    for (int p = 0; p < 4; p++)
                        asm("fma.rn.f32x2 %0, %1, %2, %0;"
                            : "+l"(acc[oo][p]) : "l"(ww), "l"(xp[2 * p + k]));
                }
            }
        }
        __syncthreads();
    }

    const int obase = b * Cn + ob * OT + ty * 4;
    #pragma unroll
    for (int oo = 0; oo < 4; oo++) {
        float* orow = out + (size_t)(obase + oo) * Tn + t0 + tx * 8;
        #pragma unroll
        for (int p = 0; p < 4; p++) {
            float lo, hi;
            asm("mov.b64 {%0, %1}, %2;" : "=f"(lo), "=f"(hi) : "l"(acc[oo][p]));
            reinterpret_cast<float2*>(orow)[p] = make_float2(lo, hi);
        }
    }
}

// ---------------------------------------------------------------------------
extern "C" void kernel_launch(void* const* d_in, const int* in_sizes, int n_in,
                              void* d_out, int out_size) {
    const float* x    = (const float*)d_in[0];
    const int*   lens = (const int*)  d_in[1];
    const float* w1   = (const float*)d_in[2];
    const float* b1   = (const float*)d_in[3];
    const float* w2   = (const float*)d_in[4];
    float* out = (float*)d_out;

    cudaFuncSetAttribute(conv_kernel,
                         cudaFuncAttributeMaxDynamicSharedMemorySize, SMEM_BYTES);

    gap_kernel<<<Bn * Cn, 256>>>(x, lens);
    fc1_kernel<<<Bn, 256>>>(w1, b1);
    wd_kernel<<<(Bn * 2 * NCH * WTILE) / 256, 256>>>(w2);
    conv_kernel<<<dim3(Tn / TT, Cn / OT, Bn), 256, SMEM_BYTES>>>(x, out);
}